// round 14
// baseline (speedup 1.0000x reference)
#include <cuda_runtime.h>
#include <cuda_fp16.h>
#include <cstdint>

// Problem constants
#define BB 2
#define SS 2048
#define VV 32000
#define HH 512
#define GG 1536
#define LL 3
#define RR (BB*SS)
#define NCH 64
#define CL  (SS/NCH)   // 32
#define KDIM 512

// ---------------- scratch ----------------
__device__ __align__(128) float g_x[RR * HH];
__device__ __align__(128) float g_gates[RR * GG];
__device__ __align__(128) float g_hl[RR * HH];
__device__ __align__(128) float g_P[RR * HH];
__device__ __align__(128) float g_aggF[BB * NCH * HH];
__device__ __align__(128) float g_aggH[BB * NCH * HH];
__device__ __align__(128) float g_carry[BB * NCH * HH];
__device__ __align__(128) __half g_xn[RR * HH];
__device__ __align__(128) __half g_wsh[LL * GG * HH];
__device__ __align__(128) __half g_fch[(size_t)VV * HH];

// ---------------- helpers ----------------
__device__ __forceinline__ uint32_t smem_u32(const void* p) {
    uint32_t a;
    asm("{ .reg .u64 t; cvta.to.shared.u64 t, %1; cvt.u32.u64 %0, t; }" : "=r"(a) : "l"(p));
    return a;
}
__device__ __forceinline__ void ldsm4(uint32_t* r, uint32_t addr) {
    asm volatile("ldmatrix.sync.aligned.m8n8.x4.shared.b16 {%0,%1,%2,%3}, [%4];"
        : "=r"(r[0]), "=r"(r[1]), "=r"(r[2]), "=r"(r[3]) : "r"(addr));
}
__device__ __forceinline__ void mma16816(float* d, const uint32_t* a, const uint32_t* b) {
    asm volatile("mma.sync.aligned.m16n8k16.row.col.f32.f16.f16.f32 "
        "{%0,%1,%2,%3}, {%4,%5,%6,%7}, {%8,%9}, {%0,%1,%2,%3};"
        : "+f"(d[0]), "+f"(d[1]), "+f"(d[2]), "+f"(d[3])
        : "r"(a[0]), "r"(a[1]), "r"(a[2]), "r"(a[3]), "r"(b[0]), "r"(b[1]));
}
__device__ __forceinline__ void cp16(uint32_t dst, const void* src) {
    asm volatile("cp.async.cg.shared.global [%0], [%1], 16;" :: "r"(dst), "l"(src));
}

// ---------------- fp16 tensor-core GEMM (R6/R11 config + PDL B-prefetch) --------
// CTA tile 128x128, 4 warps (2x2), warp tile 64x64, K staged 64, 3-stage cp.async.
// B (weights) is ready before launch (strict event dep), so B-halves of stages
// 0,1 are prefetched BEFORE cudaGridDependencySynchronize(); A-halves after.
#define STB (32 * 1024)
#define NSTAGE 3
#define GSMEM_TOTAL (NSTAGE * STB)

template<bool STREAM>
__global__ __launch_bounds__(128, 2) void gemm_mma(
    const __half* __restrict__ A, const __half* __restrict__ B,
    const float* __restrict__ bias, float* __restrict__ C, int N)
{
    extern __shared__ char smem[];
    const uint32_t sb = smem_u32(smem);
    const int tid = threadIdx.x;
    const int wid = tid >> 5, lane = tid & 31;
    const int m0 = blockIdx.y * 128, n0 = blockIdx.x * 128;
    const int wm = wid & 1, wn = wid >> 1;

    const char* baseA = (const char*)A + (size_t)m0 * (KDIM * 2);
    const char* baseB = (const char*)B + (size_t)n0 * (KDIM * 2);

    // A-half loader: rows 0..127 of a stage (it 0..7)
    auto load_A = [&](int kc, int buf) {
        const int kb = kc * 128;
        const uint32_t sp = sb + buf * STB;
#pragma unroll
        for (int it = 0; it < 8; it++) {
            int idx = tid + it * 128;        // 0..1023
            int lr = idx >> 3, c = idx & 7;
            const char* g = baseA + (size_t)lr * (KDIM * 2) + kb + c * 16;
            uint32_t bo = (uint32_t)(lr * 128 + c * 16);
            bo ^= (bo >> 3) & 0x70;
            cp16(sp + bo, g);
        }
    };
    // B-half loader: rows 0..127 of B region (it 8..15)
    auto load_B = [&](int kc, int buf) {
        const int kb = kc * 128;
        const uint32_t sp = sb + buf * STB;
#pragma unroll
        for (int it = 0; it < 8; it++) {
            int idx = tid + it * 128;        // 0..1023
            int lr = idx >> 3, c = idx & 7;
            const char* g = baseB + (size_t)lr * (KDIM * 2) + kb + c * 16;
            uint32_t bo = (uint32_t)(lr * 128 + c * 16);
            bo ^= (bo >> 3) & 0x70;
            cp16(sp + 16384 + bo, g);
        }
    };
    auto commit = [] { asm volatile("cp.async.commit_group;" ::: "memory"); };

    float acc[4][8][4];
#pragma unroll
    for (int i = 0; i < 4; i++)
#pragma unroll
        for (int j = 0; j < 8; j++)
#pragma unroll
            for (int q = 0; q < 4; q++) acc[i][j][q] = 0.f;

    // ---- PDL prologue: prefetch B (ready before launch) while predecessor drains
    load_B(0, 0);
    load_B(1, 1);

    cudaGridDependencySynchronize();   // A (xn) now safe to read

    load_A(0, 0); commit();            // group0 = B0 + B1 + A0  -> stage0 ready
    load_A(1, 1); commit();            // group1 = A1            -> stage1 ready

    const int quad = lane >> 3, r8 = lane & 7;

    for (int kc = 0; kc < 8; kc++) {
        if (kc < 7) {
            asm volatile("cp.async.wait_group 1;" ::: "memory");
        } else {
            asm volatile("cp.async.wait_group 0;" ::: "memory");
        }
        __syncthreads();

        const uint32_t sp = sb + (kc % NSTAGE) * STB;
#pragma unroll
        for (int ks = 0; ks < 4; ks++) {
            const int colA = ks * 32 + (quad >> 1) * 16;
            const int colB = ks * 32 + (quad & 1) * 16;

            uint32_t af[4][4];
#pragma unroll
            for (int i = 0; i < 4; i++) {
                int row = wm * 64 + i * 16 + r8 + (quad & 1) * 8;
                uint32_t bo = (uint32_t)(row * 128 + colA);
                bo ^= (bo >> 3) & 0x70;
                ldsm4(af[i], sp + bo);
            }
            uint32_t bf[4][4];
#pragma unroll
            for (int j4 = 0; j4 < 4; j4++) {
                int row = wn * 64 + j4 * 16 + r8 + (quad >> 1) * 8;
                uint32_t bo = (uint32_t)(row * 128 + colB);
                bo ^= (bo >> 3) & 0x70;
                ldsm4(bf[j4], sp + 16384 + bo);
            }
#pragma unroll
            for (int i = 0; i < 4; i++)
#pragma unroll
                for (int j = 0; j < 8; j++)
                    mma16816(acc[i][j], af[i], &bf[j >> 1][(j & 1) * 2]);
        }

        if (kc + 2 < 8) {
            load_A(kc + 2, (kc + 2) % NSTAGE);
            load_B(kc + 2, (kc + 2) % NSTAGE);
            commit();
        }
    }

    const int tq = lane >> 2, tr = lane & 3;
#pragma unroll
    for (int i = 0; i < 4; i++) {
        int mrow = m0 + wm * 64 + i * 16;
#pragma unroll
        for (int j = 0; j < 8; j++) {
            int col = n0 + wn * 64 + j * 8 + tr * 2;
            float b0 = __ldg(bias + col), b1 = __ldg(bias + col + 1);
            float2 v0 = { acc[i][j][0] + b0, acc[i][j][1] + b1 };
            float2 v1 = { acc[i][j][2] + b0, acc[i][j][3] + b1 };
            float* p0 = C + (size_t)(mrow + tq) * N + col;
            float* p1 = C + (size_t)(mrow + tq + 8) * N + col;
            if (STREAM) { __stcs((float2*)p0, v0); __stcs((float2*)p1, v1); }
            else        { *(float2*)p0 = v0;       *(float2*)p1 = v1; }
        }
    }
}

// ---------------- fp32 -> fp16 convert ----------------
__global__ void convert_kernel(const float* __restrict__ w,
                               __half* __restrict__ o, int n4) {
    int i = blockIdx.x * 256 + threadIdx.x;
    if (i >= n4) return;
    float4 v = __ldg((const float4*)w + i);
    __half2 p0 = { __float2half_rn(v.x), __float2half_rn(v.y) };
    __half2 p1 = { __float2half_rn(v.z), __float2half_rn(v.w) };
    ((__half2*)o)[i * 2] = p0;
    ((__half2*)o)[i * 2 + 1] = p1;
}

// ---------------- shared LN tail ----------------
__device__ __forceinline__ void ln_tail(float4* v, float s, float s2, int lane,
                                        const float* __restrict__ w,
                                        const float* __restrict__ bptr, int hasB,
                                        __half* __restrict__ out, size_t rowbase) {
#pragma unroll
    for (int o = 16; o > 0; o >>= 1) {
        s  += __shfl_xor_sync(0xffffffffu, s, o);
        s2 += __shfl_xor_sync(0xffffffffu, s2, o);
    }
    float mean = s * (1.f / HH);
    float var  = s2 * (1.f / HH) - mean * mean;
    float rs = rsqrtf(var + 1e-5f);

    __half2* oh = (__half2*)(out + rowbase);
    const float4* w4 = (const float4*)w;
    const float4* b4 = (const float4*)bptr;
#pragma unroll
    for (int r = 0; r < 4; r++) {
        float4 ww = w4[lane + r * 32];
        float4 o;
        o.x = (v[r].x - mean) * rs * ww.x;
        o.y = (v[r].y - mean) * rs * ww.y;
        o.z = (v[r].z - mean) * rs * ww.z;
        o.w = (v[r].w - mean) * rs * ww.w;
        if (hasB) {
            float4 bb = b4[lane + r * 32];
            o.x += bb.x; o.y += bb.y; o.z += bb.z; o.w += bb.w;
        }
        __half2 p0 = { __float2half_rn(o.x), __float2half_rn(o.y) };
        __half2 p1 = { __float2half_rn(o.z), __float2half_rn(o.w) };
        int e2 = (lane + r * 32) * 2;
        oh[e2] = p0; oh[e2 + 1] = p1;
    }
}

// ---------------- fused embedding gather + LN0 ----------------
__global__ __launch_bounds__(256) void embed_ln_kernel(
    const int* __restrict__ ids, const float* __restrict__ emb,
    float* __restrict__ x, __half* __restrict__ xn,
    const float* __restrict__ w, const float* __restrict__ bptr) {
    cudaGridDependencySynchronize();
    int gw = (blockIdx.x * 256 + threadIdx.x) >> 5;
    int lane = threadIdx.x & 31;
    int id = __ldg(ids + gw);
    const float4* src = (const float4*)(emb + (size_t)id * HH);
    float4* xr = (float4*)(x + (size_t)gw * HH);

    float4 v[4];
    float s = 0.f, s2 = 0.f;
#pragma unroll
    for (int r = 0; r < 4; r++) {
        v[r] = src[lane + r * 32];
        xr[lane + r * 32] = v[r];
        s  += v[r].x + v[r].y + v[r].z + v[r].w;
        s2 += v[r].x * v[r].x + v[r].y * v[r].y + v[r].z * v[r].z + v[r].w * v[r].w;
    }
    ln_tail(v, s, s2, lane, w, bptr, 1, xn, (size_t)gw * HH);
}

// ---------------- fused apply + residual + LN ----------------
__global__ __launch_bounds__(256) void apply_ln_kernel(
    const float* __restrict__ hl, const float* __restrict__ P,
    const float* __restrict__ carry, float* __restrict__ x,
    __half* __restrict__ xn,
    const float* __restrict__ w, const float* __restrict__ bptr, int hasB) {
    cudaGridDependencySynchronize();
    int gw = (blockIdx.x * 256 + threadIdx.x) >> 5;
    int lane = threadIdx.x & 31;
    int b = gw >> 11, t = gw & (SS - 1), j = t >> 5;  // CL = 32
    size_t base = (size_t)gw * HH;
    const float4* hl4 = (const float4*)(hl + base);
    const float4* P4  = (const float4*)(P + base);
    const float4* cy4 = (const float4*)(carry + (size_t)(b * NCH + j) * HH);
    float4* x4 = (float4*)(x + base);

    float4 v[4];
    float s = 0.f, s2 = 0.f;
#pragma unroll
    for (int r = 0; r < 4; r++) {
        int e = lane + r * 32;
        float4 xv = x4[e], hv = hl4[e], pv = P4[e], cv = cy4[e];
        v[r].x = fmaf(cv.x, pv.x, hv.x) + xv.x;
        v[r].y = fmaf(cv.y, pv.y, hv.y) + xv.y;
        v[r].z = fmaf(cv.z, pv.z, hv.z) + xv.z;
        v[r].w = fmaf(cv.w, pv.w, hv.w) + xv.w;
        x4[e] = v[r];
        s  += v[r].x + v[r].y + v[r].z + v[r].w;
        s2 += v[r].x * v[r].x + v[r].y * v[r].y + v[r].z * v[r].z + v[r].w * v[r].w;
    }
    ln_tail(v, s, s2, lane, w, bptr, hasB, xn, base);
}

// ---------------- gate math + chunk-local scan ----------------
__global__ void gatescan_kernel(const float* __restrict__ gates,
                                float* __restrict__ hl, float* __restrict__ P,
                                float* __restrict__ aggF, float* __restrict__ aggH) {
    cudaGridDependencySynchronize();
    int c = blockIdx.x * 128 + threadIdx.x;
    int j = blockIdx.y;
    int b = blockIdx.z;
    size_t row0 = (size_t)b * SS + (size_t)j * CL;

    float h = 0.f, p = 1.f;
#pragma unroll 4
    for (int t = 0; t < CL; t++) {
        size_t r = row0 + t;
        const float* gp = gates + r * GG;
        float fg = gp[c], ig = gp[HH + c], td = gp[2 * HH + c];
        float ea = __expf(-fg), eb = __expf(-ig);
        float inv = __fdividef(1.0f, 2.0f + ea + eb);
        float f = (1.0f + eb) * inv;
        float iv = (1.0f + ea) * inv;
        float g = (td >= 0.f) ? (td + 0.5f) : __fdividef(1.0f, 1.0f + __expf(-td));
        float v = iv * g;
        h = fmaf(f, h, v);
        p *= f;
        hl[r * HH + c] = h;
        P[r * HH + c]  = p;
    }
    int ai = (b * NCH + j) * HH + c;
    aggF[ai] = p;
    aggH[ai] = h;
}

__global__ void combine_kernel(const float* __restrict__ aggF,
                               const float* __restrict__ aggH,
                               float* __restrict__ carry) {
    cudaGridDependencySynchronize();
    int idx = blockIdx.x * blockDim.x + threadIdx.x;
    if (idx >= BB * HH) return;
    int b = idx / HH, c = idx % HH;
    float cy = 0.5f;
#pragma unroll 8
    for (int j = 0; j < NCH; j++) {
        int ai = (b * NCH + j) * HH + c;
        carry[ai] = cy;
        cy = aggH[ai] + cy * aggF[ai];
    }
}

// ---------------- host launcher ----------------
extern "C" void kernel_launch(void* const* d_in, const int* in_sizes, int n_in,
                              void* d_out, int out_size) {
    const int*   ids   = (const int*)d_in[0];
    const float* emb   = (const float*)d_in[1];
    const float* Ws    = (const float*)d_in[2];
    const float* bs    = (const float*)d_in[3];
    const float* ln_w  = (const float*)d_in[4];
    const float* ln_b  = (const float*)d_in[5];
    const float* fln_w = (const float*)d_in[6];
    const float* fc_w  = (const float*)d_in[7];
    const float* fc_b  = (const float*)d_in[8];
    float* out = (float*)d_out;

    float *px, *pgates, *phl, *pP, *paggF, *paggH, *pcarry;
    __half *pxn, *pwsh, *pfch;
    cudaGetSymbolAddress((void**)&px,     g_x);
    cudaGetSymbolAddress((void**)&pgates, g_gates);
    cudaGetSymbolAddress((void**)&phl,    g_hl);
    cudaGetSymbolAddress((void**)&pP,     g_P);
    cudaGetSymbolAddress((void**)&paggF,  g_aggF);
    cudaGetSymbolAddress((void**)&paggH,  g_aggH);
    cudaGetSymbolAddress((void**)&pcarry, g_carry);
    cudaGetSymbolAddress((void**)&pxn,    g_xn);
    cudaGetSymbolAddress((void**)&pwsh,   g_wsh);
    cudaGetSymbolAddress((void**)&pfch,   g_fch);

    cudaFuncSetAttribute(gemm_mma<false>, cudaFuncAttributeMaxDynamicSharedMemorySize, GSMEM_TOTAL);
    cudaFuncSetAttribute(gemm_mma<true>,  cudaFuncAttributeMaxDynamicSharedMemorySize, GSMEM_TOTAL);

    // Side stream + events (fork/join captured into the graph).
    static cudaStream_t s2 = nullptr;
    static cudaEvent_t evFork = nullptr, evJoinW = nullptr, evJoinFc = nullptr;
    if (s2 == nullptr) {
        cudaStreamCreateWithFlags(&s2, cudaStreamNonBlocking);
        cudaEventCreateWithFlags(&evFork,   cudaEventDisableTiming);
        cudaEventCreateWithFlags(&evJoinW,  cudaEventDisableTiming);
        cudaEventCreateWithFlags(&evJoinFc, cudaEventDisableTiming);
    }

    // PDL launch config helper (main stream, stream 0)
    cudaLaunchAttribute pdlAttr[1];
    pdlAttr[0].id = cudaLaunchAttributeProgrammaticStreamSerialization;
    pdlAttr[0].val.programmaticStreamSerializationAllowed = 1;
    auto cfg = [&](dim3 g, dim3 b, size_t sm) {
        cudaLaunchConfig_t c = {};
        c.gridDim = g; c.blockDim = b; c.dynamicSmemBytes = sm; c.stream = 0;
        c.attrs = pdlAttr; c.numAttrs = 1;
        return c;
    };

    // ---- fork: Ws convert (small, needed first) then fc_w convert, side stream ----
    cudaEventRecord(evFork, 0);
    cudaStreamWaitEvent(s2, evFork, 0);
    {
        int n4 = LL * GG * HH / 4;
        convert_kernel<<<(n4 + 255) / 256, 256, 0, s2>>>(Ws, pwsh, n4);
        cudaEventRecord(evJoinW, s2);
        int m4 = VV * HH / 4;
        convert_kernel<<<(m4 + 255) / 256, 256, 0, s2>>>(fc_w, pfch, m4);
        cudaEventRecord(evJoinFc, s2);
    }

    // ---- main stream ----
    {
        cudaLaunchConfig_t c = cfg(dim3(RR / 8), dim3(256), 0);
        cudaLaunchKernelEx(&c, embed_ln_kernel, ids, emb, px, pxn, ln_w, ln_b);
    }

    // Ws weights must be converted before the first gates GEMM (strict edge —
    // this is what makes the pre-gridsync B prefetch safe).
    cudaStreamWaitEvent(0, evJoinW, 0);

    for (int l = 0; l < LL; l++) {
        {
            cudaLaunchConfig_t c = cfg(dim3(GG / 128, RR / 128), dim3(128), GSMEM_TOTAL);
            cudaLaunchKernelEx(&c, gemm_mma<false>,
                               (const __half*)pxn, (const __half*)(pwsh + (size_t)l * GG * HH),
                               (const float*)(bs + l * GG), pgates, (int)GG);
        }
        {
            cudaLaunchConfig_t c = cfg(dim3(HH / 128, NCH, BB), dim3(128), 0);
            cudaLaunchKernelEx(&c, gatescan_kernel,
                               (const float*)pgates, phl, pP, paggF, paggH);
        }
        {
            cudaLaunchConfig_t c = cfg(dim3((BB * HH + 255) / 256), dim3(256), 0);
            cudaLaunchKernelEx(&c, combine_kernel,
                               (const float*)paggF, (const float*)paggH, pcarry);
        }
        {
            const float* lw = (l + 1 < LL) ? (ln_w + (l + 1) * HH) : fln_w;
            const float* lb = (l + 1 < LL) ? (ln_b + (l + 1) * HH) : nullptr;
            int hasB = (l + 1 < LL) ? 1 : 0;
            cudaLaunchConfig_t c = cfg(dim3(RR / 8), dim3(256), 0);
            cudaLaunchKernelEx(&c, apply_ln_kernel,
                               (const float*)phl, (const float*)pP, (const float*)pcarry,
                               px, pxn, lw, lb, hasB);
        }
    }

    // fc_w convert must be done before the final GEMM (strict edge)
    cudaStreamWaitEvent(0, evJoinFc, 0);

    {
        cudaLaunchConfig_t c = cfg(dim3(VV / 128, RR / 128), dim3(128), GSMEM_TOTAL);
        cudaLaunchKernelEx(&c, gemm_mma<true>,
                           (const __half*)pxn, (const __half*)pfch,
                           (const float*)fc_b, out, (int)VV);
    }
}

// round 16
// speedup vs baseline: 1.5315x; 1.5315x over previous
#include <cuda_runtime.h>
#include <cuda_fp16.h>
#include <cstdint>

// Problem constants
#define BB 2
#define SS 2048
#define VV 32000
#define HH 512
#define GG 1536
#define LL 3
#define RR (BB*SS)
#define NCH 64
#define CL  (SS/NCH)   // 32
#define KDIM 512

// ---------------- scratch ----------------
__device__ __align__(128) float g_x[RR * HH];
__device__ __align__(128) float g_gates[RR * GG];
__device__ __align__(128) float g_hl[RR * HH];
__device__ __align__(128) float g_P[RR * HH];
__device__ __align__(128) float g_aggF[BB * NCH * HH];
__device__ __align__(128) float g_aggH[BB * NCH * HH];
__device__ __align__(128) float g_carry[BB * NCH * HH];
__device__ __align__(128) __half g_xn[RR * HH];
__device__ __align__(128) __half g_wsh[LL * GG * HH];
__device__ __align__(128) __half g_fch[(size_t)VV * HH];

// ---------------- helpers ----------------
__device__ __forceinline__ uint32_t smem_u32(const void* p) {
    uint32_t a;
    asm("{ .reg .u64 t; cvta.to.shared.u64 t, %1; cvt.u32.u64 %0, t; }" : "=r"(a) : "l"(p));
    return a;
}
__device__ __forceinline__ void ldsm4(uint32_t* r, uint32_t addr) {
    asm volatile("ldmatrix.sync.aligned.m8n8.x4.shared.b16 {%0,%1,%2,%3}, [%4];"
        : "=r"(r[0]), "=r"(r[1]), "=r"(r[2]), "=r"(r[3]) : "r"(addr));
}
__device__ __forceinline__ void mma16816(float* d, const uint32_t* a, const uint32_t* b) {
    asm volatile("mma.sync.aligned.m16n8k16.row.col.f32.f16.f16.f32 "
        "{%0,%1,%2,%3}, {%4,%5,%6,%7}, {%8,%9}, {%0,%1,%2,%3};"
        : "+f"(d[0]), "+f"(d[1]), "+f"(d[2]), "+f"(d[3])
        : "r"(a[0]), "r"(a[1]), "r"(a[2]), "r"(a[3]), "r"(b[0]), "r"(b[1]));
}
__device__ __forceinline__ void cp16(uint32_t dst, const void* src) {
    asm volatile("cp.async.cg.shared.global [%0], [%1], 16;" :: "r"(dst), "l"(src));
}

// ---------------- fp16 tensor-core GEMM (R13 champion, verbatim) ----------------
// CTA tile 128x128, 4 warps (2x2), warp tile 64x64, K staged 64, 3-stage cp.async.
#define STB (32 * 1024)
#define NSTAGE 3
#define GSMEM_TOTAL (NSTAGE * STB)

template<bool STREAM>
__global__ __launch_bounds__(128, 2) void gemm_mma(
    const __half* __restrict__ A, const __half* __restrict__ B,
    const float* __restrict__ bias, float* __restrict__ C, int N)
{
    // PDL: wait for predecessor's writes before reading A/B.
    cudaGridDependencySynchronize();

    extern __shared__ char smem[];
    const uint32_t sb = smem_u32(smem);
    const int tid = threadIdx.x;
    const int wid = tid >> 5, lane = tid & 31;
    const int m0 = blockIdx.y * 128, n0 = blockIdx.x * 128;
    const int wm = wid & 1, wn = wid >> 1;

    const char* baseA = (const char*)A + (size_t)m0 * (KDIM * 2);
    const char* baseB = (const char*)B + (size_t)n0 * (KDIM * 2);

    float acc[4][8][4];
#pragma unroll
    for (int i = 0; i < 4; i++)
#pragma unroll
        for (int j = 0; j < 8; j++)
#pragma unroll
            for (int q = 0; q < 4; q++) acc[i][j][q] = 0.f;

    auto load_stage = [&](int kc, int buf) {
        const int kb = kc * 128;
        const uint32_t sp = sb + buf * STB;
#pragma unroll
        for (int it = 0; it < 16; it++) {
            int idx = tid + it * 128;
            int r = idx >> 3, c = idx & 7;
            const char* src; uint32_t roff; int lr;
            if (r < 128) { src = baseA; roff = 0;     lr = r; }
            else         { src = baseB; roff = 16384; lr = r - 128; }
            const char* g = src + (size_t)lr * (KDIM * 2) + kb + c * 16;
            uint32_t bo = (uint32_t)(lr * 128 + c * 16);
            bo ^= (bo >> 3) & 0x70;
            cp16(sp + roff + bo, g);
        }
        asm volatile("cp.async.commit_group;" ::: "memory");
    };

    const int quad = lane >> 3, r8 = lane & 7;

    load_stage(0, 0);
    load_stage(1, 1);

    for (int kc = 0; kc < 8; kc++) {
        if (kc < 7) {
            asm volatile("cp.async.wait_group 1;" ::: "memory");
        } else {
            asm volatile("cp.async.wait_group 0;" ::: "memory");
        }
        __syncthreads();

        const uint32_t sp = sb + (kc % NSTAGE) * STB;
#pragma unroll
        for (int ks = 0; ks < 4; ks++) {
            const int colA = ks * 32 + (quad >> 1) * 16;
            const int colB = ks * 32 + (quad & 1) * 16;

            uint32_t af[4][4];
#pragma unroll
            for (int i = 0; i < 4; i++) {
                int row = wm * 64 + i * 16 + r8 + (quad & 1) * 8;
                uint32_t bo = (uint32_t)(row * 128 + colA);
                bo ^= (bo >> 3) & 0x70;
                ldsm4(af[i], sp + bo);
            }
            uint32_t bf[4][4];
#pragma unroll
            for (int j4 = 0; j4 < 4; j4++) {
                int row = wn * 64 + j4 * 16 + r8 + (quad >> 1) * 8;
                uint32_t bo = (uint32_t)(row * 128 + colB);
                bo ^= (bo >> 3) & 0x70;
                ldsm4(bf[j4], sp + 16384 + bo);
            }
#pragma unroll
            for (int i = 0; i < 4; i++)
#pragma unroll
                for (int j = 0; j < 8; j++)
                    mma16816(acc[i][j], af[i], &bf[j >> 1][(j & 1) * 2]);
        }

        if (kc + 2 < 8) load_stage(kc + 2, (kc + 2) % NSTAGE);
    }

    const int tq = lane >> 2, tr = lane & 3;
#pragma unroll
    for (int i = 0; i < 4; i++) {
        int mrow = m0 + wm * 64 + i * 16;
#pragma unroll
        for (int j = 0; j < 8; j++) {
            int col = n0 + wn * 64 + j * 8 + tr * 2;
            float b0 = __ldg(bias + col), b1 = __ldg(bias + col + 1);
            float2 v0 = { acc[i][j][0] + b0, acc[i][j][1] + b1 };
            float2 v1 = { acc[i][j][2] + b0, acc[i][j][3] + b1 };
            float* p0 = C + (size_t)(mrow + tq) * N + col;
            float* p1 = C + (size_t)(mrow + tq + 8) * N + col;
            if (STREAM) { __stcs((float2*)p0, v0); __stcs((float2*)p1, v1); }
            else        { *(float2*)p0 = v0;       *(float2*)p1 = v1; }
        }
    }
}

// ---------------- fp32 -> fp16 convert ----------------
__global__ void convert_kernel(const float* __restrict__ w,
                               __half* __restrict__ o, int n4) {
    int i = blockIdx.x * 256 + threadIdx.x;
    if (i >= n4) return;
    float4 v = __ldg((const float4*)w + i);
    __half2 p0 = { __float2half_rn(v.x), __float2half_rn(v.y) };
    __half2 p1 = { __float2half_rn(v.z), __float2half_rn(v.w) };
    ((__half2*)o)[i * 2] = p0;
    ((__half2*)o)[i * 2 + 1] = p1;
}

// ---------------- shared LN tail ----------------
__device__ __forceinline__ void ln_tail(float4* v, float s, float s2, int lane,
                                        const float* __restrict__ w,
                                        const float* __restrict__ bptr, int hasB,
                                        __half* __restrict__ out, size_t rowbase) {
#pragma unroll
    for (int o = 16; o > 0; o >>= 1) {
        s  += __shfl_xor_sync(0xffffffffu, s, o);
        s2 += __shfl_xor_sync(0xffffffffu, s2, o);
    }
    float mean = s * (1.f / HH);
    float var  = s2 * (1.f / HH) - mean * mean;
    float rs = rsqrtf(var + 1e-5f);

    __half2* oh = (__half2*)(out + rowbase);
    const float4* w4 = (const float4*)w;
    const float4* b4 = (const float4*)bptr;
#pragma unroll
    for (int r = 0; r < 4; r++) {
        float4 ww = w4[lane + r * 32];
        float4 o;
        o.x = (v[r].x - mean) * rs * ww.x;
        o.y = (v[r].y - mean) * rs * ww.y;
        o.z = (v[r].z - mean) * rs * ww.z;
        o.w = (v[r].w - mean) * rs * ww.w;
        if (hasB) {
            float4 bb = b4[lane + r * 32];
            o.x += bb.x; o.y += bb.y; o.z += bb.z; o.w += bb.w;
        }
        __half2 p0 = { __float2half_rn(o.x), __float2half_rn(o.y) };
        __half2 p1 = { __float2half_rn(o.z), __float2half_rn(o.w) };
        int e2 = (lane + r * 32) * 2;
        oh[e2] = p0; oh[e2 + 1] = p1;
    }
}

// ---------------- fused embedding gather + LN0 ----------------
__global__ __launch_bounds__(256) void embed_ln_kernel(
    const int* __restrict__ ids, const float* __restrict__ emb,
    float* __restrict__ x, __half* __restrict__ xn,
    const float* __restrict__ w, const float* __restrict__ bptr) {
    cudaGridDependencySynchronize();
    int gw = (blockIdx.x * 256 + threadIdx.x) >> 5;
    int lane = threadIdx.x & 31;
    int id = __ldg(ids + gw);
    const float4* src = (const float4*)(emb + (size_t)id * HH);
    float4* xr = (float4*)(x + (size_t)gw * HH);

    float4 v[4];
    float s = 0.f, s2 = 0.f;
#pragma unroll
    for (int r = 0; r < 4; r++) {
        v[r] = src[lane + r * 32];
        xr[lane + r * 32] = v[r];
        s  += v[r].x + v[r].y + v[r].z + v[r].w;
        s2 += v[r].x * v[r].x + v[r].y * v[r].y + v[r].z * v[r].z + v[r].w * v[r].w;
    }
    ln_tail(v, s, s2, lane, w, bptr, 1, xn, (size_t)gw * HH);
}

// ---------------- fused apply + residual + LN (fp32 hl/P; optional x write) ----
__global__ __launch_bounds__(256) void apply_ln_kernel(
    const float* __restrict__ hl, const float* __restrict__ P,
    const float* __restrict__ carry, float* __restrict__ x,
    __half* __restrict__ xn,
    const float* __restrict__ w, const float* __restrict__ bptr,
    int hasB, int writeX) {
    cudaGridDependencySynchronize();
    int gw = (blockIdx.x * 256 + threadIdx.x) >> 5;
    int lane = threadIdx.x & 31;
    int b = gw >> 11, t = gw & (SS - 1), j = t >> 5;  // CL = 32
    size_t base = (size_t)gw * HH;
    const float4* hl4 = (const float4*)(hl + base);
    const float4* P4  = (const float4*)(P + base);
    const float4* cy4 = (const float4*)(carry + (size_t)(b * NCH + j) * HH);
    float4* x4 = (float4*)(x + base);

    float4 v[4];
    float s = 0.f, s2 = 0.f;
#pragma unroll
    for (int r = 0; r < 4; r++) {
        int e = lane + r * 32;
        float4 xv = x4[e], hv = hl4[e], pv = P4[e], cv = cy4[e];
        v[r].x = fmaf(cv.x, pv.x, hv.x) + xv.x;
        v[r].y = fmaf(cv.y, pv.y, hv.y) + xv.y;
        v[r].z = fmaf(cv.z, pv.z, hv.z) + xv.z;
        v[r].w = fmaf(cv.w, pv.w, hv.w) + xv.w;
        if (writeX) x4[e] = v[r];
        s  += v[r].x + v[r].y + v[r].z + v[r].w;
        s2 += v[r].x * v[r].x + v[r].y * v[r].y + v[r].z * v[r].z + v[r].w * v[r].w;
    }
    ln_tail(v, s, s2, lane, w, bptr, hasB, xn, base);
}

// ---------------- gate math + chunk-local scan (fp32) ----------------
__global__ void gatescan_kernel(const float* __restrict__ gates,
                                float* __restrict__ hl, float* __restrict__ P,
                                float* __restrict__ aggF, float* __restrict__ aggH) {
    cudaGridDependencySynchronize();
    int c = blockIdx.x * 128 + threadIdx.x;
    int j = blockIdx.y;
    int b = blockIdx.z;
    size_t row0 = (size_t)b * SS + (size_t)j * CL;

    float h = 0.f, p = 1.f;
#pragma unroll 4
    for (int t = 0; t < CL; t++) {
        size_t r = row0 + t;
        const float* gp = gates + r * GG;
        float fg = gp[c], ig = gp[HH + c], td = gp[2 * HH + c];
        float ea = __expf(-fg), eb = __expf(-ig);
        float inv = __fdividef(1.0f, 2.0f + ea + eb);
        float f = (1.0f + eb) * inv;
        float iv = (1.0f + ea) * inv;
        float g = (td >= 0.f) ? (td + 0.5f) : __fdividef(1.0f, 1.0f + __expf(-td));
        float v = iv * g;
        h = fmaf(f, h, v);
        p *= f;
        hl[r * HH + c] = h;
        P[r * HH + c]  = p;
    }
    int ai = (b * NCH + j) * HH + c;
    aggF[ai] = p;
    aggH[ai] = h;
}

__global__ void combine_kernel(const float* __restrict__ aggF,
                               const float* __restrict__ aggH,
                               float* __restrict__ carry) {
    cudaGridDependencySynchronize();
    int idx = blockIdx.x * blockDim.x + threadIdx.x;
    if (idx >= BB * HH) return;
    int b = idx / HH, c = idx % HH;
    float cy = 0.5f;
#pragma unroll 8
    for (int j = 0; j < NCH; j++) {
        int ai = (b * NCH + j) * HH + c;
        carry[ai] = cy;
        cy = aggH[ai] + cy * aggF[ai];
    }
}

// ---------------- host launcher ----------------
extern "C" void kernel_launch(void* const* d_in, const int* in_sizes, int n_in,
                              void* d_out, int out_size) {
    const int*   ids   = (const int*)d_in[0];
    const float* emb   = (const float*)d_in[1];
    const float* Ws    = (const float*)d_in[2];
    const float* bs    = (const float*)d_in[3];
    const float* ln_w  = (const float*)d_in[4];
    const float* ln_b  = (const float*)d_in[5];
    const float* fln_w = (const float*)d_in[6];
    const float* fc_w  = (const float*)d_in[7];
    const float* fc_b  = (const float*)d_in[8];
    float* out = (float*)d_out;

    float *px, *pgates, *phl, *pP, *paggF, *paggH, *pcarry;
    __half *pxn, *pwsh, *pfch;
    cudaGetSymbolAddress((void**)&px,     g_x);
    cudaGetSymbolAddress((void**)&pgates, g_gates);
    cudaGetSymbolAddress((void**)&phl,    g_hl);
    cudaGetSymbolAddress((void**)&pP,     g_P);
    cudaGetSymbolAddress((void**)&paggF,  g_aggF);
    cudaGetSymbolAddress((void**)&paggH,  g_aggH);
    cudaGetSymbolAddress((void**)&pcarry, g_carry);
    cudaGetSymbolAddress((void**)&pxn,    g_xn);
    cudaGetSymbolAddress((void**)&pwsh,   g_wsh);
    cudaGetSymbolAddress((void**)&pfch,   g_fch);

    cudaFuncSetAttribute(gemm_mma<false>, cudaFuncAttributeMaxDynamicSharedMemorySize, GSMEM_TOTAL);
    cudaFuncSetAttribute(gemm_mma<true>,  cudaFuncAttributeMaxDynamicSharedMemorySize, GSMEM_TOTAL);

    // Side stream + events (fork/join captured into the graph).
    static cudaStream_t s2 = nullptr;
    static cudaEvent_t evFork = nullptr, evJoinW = nullptr, evJoinFc = nullptr;
    if (s2 == nullptr) {
        cudaStreamCreateWithFlags(&s2, cudaStreamNonBlocking);
        cudaEventCreateWithFlags(&evFork,   cudaEventDisableTiming);
        cudaEventCreateWithFlags(&evJoinW,  cudaEventDisableTiming);
        cudaEventCreateWithFlags(&evJoinFc, cudaEventDisableTiming);
    }

    // PDL launch config helper (main stream, stream 0)
    cudaLaunchAttribute pdlAttr[1];
    pdlAttr[0].id = cudaLaunchAttributeProgrammaticStreamSerialization;
    pdlAttr[0].val.programmaticStreamSerializationAllowed = 1;
    auto cfg = [&](dim3 g, dim3 b, size_t sm) {
        cudaLaunchConfig_t c = {};
        c.gridDim = g; c.blockDim = b; c.dynamicSmemBytes = sm; c.stream = 0;
        c.attrs = pdlAttr; c.numAttrs = 1;
        return c;
    };

    // ---- fork: Ws convert then fc_w convert on side stream ----
    cudaEventRecord(evFork, 0);
    cudaStreamWaitEvent(s2, evFork, 0);
    {
        int n4 = LL * GG * HH / 4;
        convert_kernel<<<(n4 + 255) / 256, 256, 0, s2>>>(Ws, pwsh, n4);
        cudaEventRecord(evJoinW, s2);
        int m4 = VV * HH / 4;
        convert_kernel<<<(m4 + 255) / 256, 256, 0, s2>>>(fc_w, pfch, m4);
        cudaEventRecord(evJoinFc, s2);
    }

    // ---- main stream ----
    {
        cudaLaunchConfig_t c = cfg(dim3(RR / 8), dim3(256), 0);
        cudaLaunchKernelEx(&c, embed_ln_kernel, ids, emb, px, pxn, ln_w, ln_b);
    }

    cudaStreamWaitEvent(0, evJoinW, 0);

    for (int l = 0; l < LL; l++) {
        {
            cudaLaunchConfig_t c = cfg(dim3(GG / 128, RR / 128), dim3(128), GSMEM_TOTAL);
            cudaLaunchKernelEx(&c, gemm_mma<false>,
                               (const __half*)pxn, (const __half*)(pwsh + (size_t)l * GG * HH),
                               (const float*)(bs + l * GG), pgates, (int)GG);
        }
        {
            cudaLaunchConfig_t c = cfg(dim3(HH / 128, NCH, BB), dim3(128), 0);
            cudaLaunchKernelEx(&c, gatescan_kernel,
                               (const float*)pgates, phl, pP, paggF, paggH);
        }
        {
            cudaLaunchConfig_t c = cfg(dim3((BB * HH + 255) / 256), dim3(256), 0);
            cudaLaunchKernelEx(&c, combine_kernel,
                               (const float*)paggF, (const float*)paggH, pcarry);
        }
        {
            const float* lw = (l + 1 < LL) ? (ln_w + (l + 1) * HH) : fln_w;
            const float* lb = (l + 1 < LL) ? (ln_b + (l + 1) * HH) : nullptr;
            int hasB = (l + 1 < LL) ? 1 : 0;
            int writeX = (l + 1 < LL) ? 1 : 0;   // last layer: x is dead after final LN
            cudaLaunchConfig_t c = cfg(dim3(RR / 8), dim3(256), 0);
            cudaLaunchKernelEx(&c, apply_ln_kernel,
                               (const float*)phl, (const float*)pP, (const float*)pcarry,
                               px, pxn, lw, lb, hasB, writeX);
        }
    }

    cudaStreamWaitEvent(0, evJoinFc, 0);

    {
        cudaLaunchConfig_t c = cfg(dim3(VV / 128, RR / 128), dim3(128), GSMEM_TOTAL);
        cudaLaunchKernelEx(&c, gemm_mma<true>,
                           (const __half*)pxn, (const __half*)pfch,
                           (const float*)fc_b, out, (int)VV);
    }
}